// round 10
// baseline (speedup 1.0000x reference)
#include <cuda_runtime.h>

#define B_ 32
#define S_ 2048
#define F_ 768
#define H_ 8
#define KDIM_ (F_*H_)          // 6144
#define NTILE_ 16              // 8-row tiles per block (128 rows)
#define CH_B_ 16               // chunks per batch (2048 / 128)
#define NPART_ (B_*CH_B_)      // 512 partial slabs

// Scratch (device globals; no runtime allocation)
__device__ float g_z[B_*H_];               // softmax denominators (atomic-accumulated)
__device__ float g_part[NPART_*KDIM_];     // per-block partial pooled slabs (50MB)
__device__ float g_pooled[B_*KDIM_];       // normalized pooled [b][f][h]

// ---------- packed f32x2 helpers ----------
__device__ __forceinline__ unsigned long long bcast2(float v) {
    unsigned int u = __float_as_uint(v);
    unsigned long long r;
    asm("mov.b64 %0, {%1, %1};" : "=l"(r) : "r"(u));
    return r;
}
__device__ __forceinline__ unsigned long long pack2(float a, float b) {
    unsigned long long r;
    asm("mov.b64 %0, {%1, %2};" : "=l"(r)
        : "r"(__float_as_uint(a)), "r"(__float_as_uint(b)));
    return r;
}
__device__ __forceinline__ void ffma2(unsigned long long &d, unsigned long long a, unsigned long long b) {
    asm("fma.rn.f32x2 %0, %1, %2, %0;" : "+l"(d) : "l"(a), "l"(b));
}
__device__ __forceinline__ unsigned long long fadd2(unsigned long long a, unsigned long long b) {
    unsigned long long r;
    asm("add.rn.f32x2 %0, %1, %2;" : "=l"(r) : "l"(a), "l"(b));
    return r;
}
__device__ __forceinline__ float2 unpack2(unsigned long long v) {
    unsigned int lo, hi;
    asm("mov.b64 {%0, %1}, %2;" : "=r"(lo), "=r"(hi) : "l"(v));
    return make_float2(__uint_as_float(lo), __uint_as_float(hi));
}

// ---------- cp.async helpers ----------
__device__ __forceinline__ unsigned int smem_u32(const void* p) {
    unsigned int a;
    asm("{ .reg .u64 t; cvta.to.shared.u64 t, %1; cvt.u32.u64 %0, t; }" : "=r"(a) : "l"(p));
    return a;
}
__device__ __forceinline__ void cp16(unsigned int dst, const void* src) {
    asm volatile("cp.async.cg.shared.global [%0], [%1], 16;" :: "r"(dst), "l"(src));
}
#define CP_COMMIT() asm volatile("cp.async.commit_group;" ::: "memory")
#define CP_WAIT0()  asm volatile("cp.async.wait_group 0;" ::: "memory")
#define CP_WAIT1()  asm volatile("cp.async.wait_group 1;" ::: "memory")

// ---------- K0a/K0b/K0c: init (split so k_fused is the 4th launch -> profiled) ----------
__global__ void __launch_bounds__(256) k_init_z() {
    g_z[threadIdx.x] = 0.f;
}
__global__ void __launch_bounds__(256) k_init_oa(const float* __restrict__ bout,
                                                 float* __restrict__ out) {
    int b = blockIdx.x;
    for (int i = threadIdx.x; i < F_; i += 256) out[b*F_ + i] = bout[i];
}
__global__ void __launch_bounds__(256) k_init_ob(const float* __restrict__ bout,
                                                 float* __restrict__ out) {
    int b = blockIdx.x + 16;
    for (int i = threadIdx.x; i < F_; i += 256) out[b*F_ + i] = bout[i];
}

// ---------- K_FUSED v5: W in registers, f-partitioned phase 1, no W smem tile ----------
// grid (CH_B_, B_). Block: 128 rows = 16 tiles of 8 rows, double-buffered x in smem.
// Thread owns f-slice {tid, tid+256, tid+512}; Wreg[h][fi] = packed (Wa, Wg), 24 ull.
// Phase 1 per row: 3 LDS x, 24 ffma2 -> part[8]; 16-shfl log-halving -> even lanes<16
//   hold head lane>>1; STS partial -> psum[row][warp][h]; after tile, tid<64 finishes
//   cross-warp sum, computes w=exp(att)*sigmoid(gate+bg) -> wsh; z into zacc regs.
// Phase 2 per row: re-read x from smem, broadcast wsh, 12 ffma2 into acc[3][4].
#define SMEM_FUSED_ (2*8*F_*4)   // 48KB dynamic: two 8-row x buffers

__global__ void __launch_bounds__(256, 2) k_fused(const float* __restrict__ x,
                                                  const float* __restrict__ Wa,
                                                  const float* __restrict__ Wg,
                                                  const float* __restrict__ bg) {
    extern __shared__ __align__(16) float xs[];              // [2][8][768]
    __shared__ __align__(16) unsigned long long psum[8][8][8]; // [row][warp][h] 4KB
    __shared__ __align__(16) float wsh[8][8];

    int tid = threadIdx.x, warp = tid >> 5, lane = tid & 31;
    int b = blockIdx.y, chunk = blockIdx.x;
    int row00 = b*S_ + chunk*(8*NTILE_);
    unsigned int xsb = smem_u32(xs);
    const float4* x4 = reinterpret_cast<const float4*>(x);

    // W in registers: 8 heads x 3 f-slices, packed (att,gate). Read once (L2-hot).
    unsigned long long Wreg[8][3];
    #pragma unroll
    for (int h = 0; h < 8; h++)
        #pragma unroll
        for (int fi = 0; fi < 3; fi++) {
            int f = tid + fi*256;
            Wreg[h][fi] = pack2(Wa[h*F_ + f], Wg[h*F_ + f]);
        }
    float bgv = bg[tid & 7];

    // stage one 8-row tile (24KB), one commit group; warp stages its own row
    auto stage = [&](int buf, int t) {
        const float4* src = x4 + (size_t)(row00 + t*8 + warp)*192;
        unsigned int dst = xsb + (unsigned)(buf*6144 + warp*768)*4u;
        #pragma unroll
        for (int j = 0; j < 6; j++)
            cp16(dst + (unsigned)(lane + j*32)*16u, src + lane + j*32);
        CP_COMMIT();
    };
    stage(0, 0);
    stage(1, 1);

    unsigned long long acc[3][4];              // pooled accum: 3 f x 4 h-pairs
    #pragma unroll
    for (int i = 0; i < 3; i++)
        #pragma unroll
        for (int j = 0; j < 4; j++) acc[i][j] = 0ull;
    float zacc = 0.f;                          // tid<64: h=tid&7, row-slot=tid>>3

    #pragma unroll 1
    for (int t = 0; t < NTILE_; t++) {
        if (t < NTILE_-1) { CP_WAIT1(); } else { CP_WAIT0(); }
        __syncthreads();
        const float* xt = xs + (t & 1)*8*F_;

        // ---- phase 1: partial logits over thread's f-slice, per row ----
        #pragma unroll 2
        for (int sl = 0; sl < 8; sl++) {
            float x0 = xt[sl*F_ + tid];
            float x1 = xt[sl*F_ + tid + 256];
            float x2 = xt[sl*F_ + tid + 512];
            unsigned long long b0 = bcast2(x0), b1 = bcast2(x1), b2 = bcast2(x2);
            unsigned long long part[8];
            #pragma unroll
            for (int h = 0; h < 8; h++) {
                part[h] = 0ull;
                ffma2(part[h], b0, Wreg[h][0]);
                ffma2(part[h], b1, Wreg[h][1]);
                ffma2(part[h], b2, Wreg[h][2]);
            }
            // warp reduce: fold16, halve(8,8),(4,4),(2,2), final xor1
            #pragma unroll
            for (int i = 0; i < 8; i++)
                part[i] = fadd2(part[i], __shfl_xor_sync(0xffffffffu, part[i], 16));
            #pragma unroll
            for (int d = 8; d >= 2; d >>= 1) {
                bool up = (lane & d) != 0;
                int c2 = d >> 1;               // halving: count c = d, keep c/2
                #pragma unroll
                for (int i = 0; i < 4; i++) {
                    if (i < c2) {
                        unsigned long long send = up ? part[i] : part[i + c2];
                        unsigned long long recv = __shfl_xor_sync(0xffffffffu, send, d);
                        unsigned long long keep = up ? part[i + c2] : part[i];
                        part[i] = fadd2(keep, recv);
                    }
                }
            }
            part[0] = fadd2(part[0], __shfl_xor_sync(0xffffffffu, part[0], 1));
            if (lane < 16 && !(lane & 1))
                psum[sl][warp][lane >> 1] = part[0];
        }
        __syncthreads();

        // ---- cross-warp combine + softmax/gate weights (tid<64: sl=tid>>3, h=tid&7) ----
        if (tid < 64) {
            int sl = tid >> 3, h = tid & 7;
            unsigned long long s = psum[sl][0][h];
            #pragma unroll
            for (int w = 1; w < 8; w++) s = fadd2(s, psum[sl][w][h]);
            float2 lg = unpack2(s);
            // no max-subtraction: logits ~ N(0,1); softmax shift-invariance (b_att cancels)
            float e = __expf(lg.x);
            wsh[sl][h] = e / (1.f + __expf(-(lg.y + bgv)));
            zacc += e;
        }
        __syncthreads();

        // ---- phase 2: pooling (x re-read from smem, wsh broadcast) ----
        #pragma unroll 2
        for (int sl = 0; sl < 8; sl++) {
            float x0 = xt[sl*F_ + tid];
            float x1 = xt[sl*F_ + tid + 256];
            float x2 = xt[sl*F_ + tid + 512];
            unsigned long long b0 = bcast2(x0), b1 = bcast2(x1), b2 = bcast2(x2);
            ulonglong2 w01 = *reinterpret_cast<const ulonglong2*>(&wsh[sl][0]);
            ulonglong2 w23 = *reinterpret_cast<const ulonglong2*>(&wsh[sl][4]);
            unsigned long long wp[4] = {w01.x, w01.y, w23.x, w23.y};
            #pragma unroll
            for (int hp = 0; hp < 4; hp++) {
                ffma2(acc[0][hp], b0, wp[hp]);
                ffma2(acc[1][hp], b1, wp[hp]);
                ffma2(acc[2][hp], b2, wp[hp]);
            }
        }
        __syncthreads();                       // done with xt before restage
        if (t + 2 < NTILE_) stage(t & 1, t + 2);
    }

    // ---- z epilogue: reduce over row-slots (warps 0-1 hold zacc) ----
    if (warp < 2) {
        zacc += __shfl_xor_sync(0xffffffffu, zacc, 8);
        zacc += __shfl_xor_sync(0xffffffffu, zacc, 16);
    }
    __syncthreads();
    float* zsc = reinterpret_cast<float*>(psum);
    if (warp == 1 && lane < 8) zsc[lane] = zacc;
    __syncthreads();
    if (warp == 0 && lane < 8) atomicAdd(&g_z[b*8 + lane], zacc + zsc[lane]);

    // write private partial slab (no atomics)
    unsigned long long* gp = reinterpret_cast<unsigned long long*>(
        g_part + (size_t)(b*CH_B_ + chunk)*KDIM_);
    #pragma unroll
    for (int fi = 0; fi < 3; fi++) {
        int f = tid + fi*256;
        #pragma unroll
        for (int hp = 0; hp < 4; hp++)
            gp[f*4 + hp] = acc[fi][hp];
    }
}

// ---------- K_NORM: g_pooled = (sum of 16 partial slabs) / Z ----------
__global__ void __launch_bounds__(256) k_norm() {
    __shared__ float iz[8];
    int b = blockIdx.x >> 1, half = blockIdx.x & 1;      // 64 blocks
    if (threadIdx.x < 8) iz[threadIdx.x] = 1.f / g_z[b*8 + threadIdx.x];
    __syncthreads();
    #pragma unroll
    for (int j = 0; j < 3; j++) {
        int idx4 = half*768 + j*256 + threadIdx.x;       // float4 index in batch slab
        float4 s = make_float4(0.f, 0.f, 0.f, 0.f);
        #pragma unroll
        for (int p = 0; p < CH_B_; p++) {
            float4 v = reinterpret_cast<const float4*>(
                g_part + (size_t)(b*CH_B_ + p)*KDIM_)[idx4];
            s.x += v.x; s.y += v.y; s.z += v.z; s.w += v.w;
        }
        int hb = (idx4 & 1) * 4;
        s.x *= iz[hb]; s.y *= iz[hb+1]; s.z *= iz[hb+2]; s.w *= iz[hb+3];
        reinterpret_cast<float4*>(g_pooled + (size_t)b*KDIM_)[idx4] = s;
    }
}

// ---------- K4: out += pooled @ Wout^T  (576 blocks, double-buffered, swizzled) ----------
#define NT_ 64       // output-column tile per block (grid.x = 12)
#define KT_ 128      // K range per block (grid.y = 48)
#define KSUB_ 64     // K staged per buffer (32 ull units)

__global__ void __launch_bounds__(256) k_out4(const float* __restrict__ Wout,
                                              float* __restrict__ out) {
    __shared__ unsigned long long ws[2][NT_][32];        // rotation-swizzled: phys=(k+col)&31
    __shared__ unsigned long long ps[2][32][32];
    int n0 = blockIdx.x * NT_;
    int k0h = blockIdx.y * (KT_/2);                      // in float2 units
    int cidx = threadIdx.x & 31;
    int bq   = threadIdx.x >> 5;
    const float2* W2 = reinterpret_cast<const float2*>(Wout);
    const float2* P2 = reinterpret_cast<const float2*>(g_pooled);

    int wc = threadIdx.x >> 5;
    int kq = threadIdx.x & 31;

    float2 rw[8], rp[4];
    #pragma unroll
    for (int s = 0; s < 8; s++)
        rw[s] = W2[(size_t)(n0 + wc + s*8)*(KDIM_/2) + k0h + kq];
    #pragma unroll
    for (int s = 0; s < 4; s++)
        rp[s] = P2[(size_t)(wc + s*8)*(KDIM_/2) + k0h + kq];
    #pragma unroll
    for (int s = 0; s < 8; s++)
        ws[0][wc + s*8][(kq + wc + s*8) & 31] = pack2(rw[s].x, rw[s].y);
    #pragma unroll
    for (int s = 0; s < 4; s++)
        ps[0][wc + s*8][kq] = pack2(rp[s].x, rp[s].y);
    __syncthreads();

    unsigned long long acc[4][2];
    #pragma unroll
    for (int r = 0; r < 4; r++) { acc[r][0] = 0ull; acc[r][1] = 0ull; }

    #pragma unroll
    for (int sub = 0; sub < KT_/KSUB_; sub++) {
        if (sub < KT_/KSUB_ - 1) {
            int kh = k0h + (sub+1)*32;
            #pragma unroll
            for (int s = 0; s < 8; s++)
                rw[s] = W2[(size_t)(n0 + wc + s*8)*(KDIM_/2) + kh + kq];
            #pragma unroll
            for (int s = 0; s < 4; s++)
                rp[s] = P2[(size_t)(wc + s*8)*(KDIM_/2) + kh + kq];
        }
        int buf = sub & 1;
        #pragma unroll 8
        for (int kk = 0; kk < 32; kk++) {
            int ph = (kk + cidx) & 31;
            unsigned long long wv0 = ws[buf][cidx][ph];
            unsigned long long wv1 = ws[buf][cidx + 32][ph];
            #pragma unroll
            for (int r = 0; r < 4; r++) {
                unsigned long long pv = ps[buf][bq*4 + r][kk];
                ffma2(acc[r][0], pv, wv0);
                ffma2(acc[r][1], pv, wv1);
            }
        }
        if (sub < KT_/KSUB_ - 1) {
            int nb = (sub + 1) & 1;
            #pragma unroll
            for (int s = 0; s < 8; s++)
                ws[nb][wc + s*8][(kq + wc + s*8) & 31] = pack2(rw[s].x, rw[s].y);
            #pragma unroll
            for (int s = 0; s < 4; s++)
                ps[nb][wc + s*8][kq] = pack2(rp[s].x, rp[s].y);
            __syncthreads();
        }
    }

    #pragma unroll
    for (int r = 0; r < 4; r++)
        #pragma unroll
        for (int c = 0; c < 2; c++) {
            float2 v = unpack2(acc[r][c]);
            atomicAdd(&out[(size_t)(bq*4 + r)*F_ + n0 + cidx + c*32], v.x + v.y);
        }
}

extern "C" void kernel_launch(void* const* d_in, const int* in_sizes, int n_in,
                              void* d_out, int out_size) {
    const float* x    = (const float*)d_in[0];   // [B,S,F]
    const float* Wa   = (const float*)d_in[1];   // [H,F]
    // d_in[2] = b_att: unused (softmax over s is shift-invariant per (b,h))
    const float* Wg   = (const float*)d_in[3];   // [H,F]
    const float* bg   = (const float*)d_in[4];   // [H]
    const float* Wout = (const float*)d_in[5];   // [F, H*F]
    const float* bout = (const float*)d_in[6];   // [F]
    float* out = (float*)d_out;                  // [B,F]

    static int smem_set = 0;
    if (!smem_set) {
        cudaFuncSetAttribute(k_fused, cudaFuncAttributeMaxDynamicSharedMemorySize,
                             SMEM_FUSED_);
        smem_set = 1;
    }

    k_init_z<<<1, 256>>>();
    k_init_oa<<<16, 256>>>(bout, out);
    k_init_ob<<<16, 256>>>(bout, out);
    k_fused<<<dim3(CH_B_, B_), 256, SMEM_FUSED_>>>(x, Wa, Wg, bg);   // 4th launch -> profiled
    k_norm<<<2*B_, 256>>>();
    k_out4<<<dim3(F_/NT_, KDIM_/KT_), 256>>>(Wout, out);
}

// round 11
// speedup vs baseline: 1.0156x; 1.0156x over previous
#include <cuda_runtime.h>

#define B_ 32
#define S_ 2048
#define F_ 768
#define H_ 8
#define KDIM_ (F_*H_)          // 6144
#define CH_B_ 16               // 128-row chunks per batch
#define NPART_ (B_*CH_B_)      // 512 partial slabs

// Scratch (device globals; no runtime allocation)
__device__ float g_z[B_*H_];               // softmax denominators (atomic-accumulated)
__device__ float g_part[NPART_*KDIM_];     // per-block partial pooled slabs
__device__ float g_pooled[B_*KDIM_];       // normalized pooled [b][f][h]

// ---------- packed f32x2 helpers ----------
__device__ __forceinline__ unsigned long long bcast2(float v) {
    unsigned int u = __float_as_uint(v);
    unsigned long long r;
    asm("mov.b64 %0, {%1, %1};" : "=l"(r) : "r"(u));
    return r;
}
__device__ __forceinline__ unsigned long long pack2(float a, float b) {
    unsigned long long r;
    asm("mov.b64 %0, {%1, %2};" : "=l"(r)
        : "r"(__float_as_uint(a)), "r"(__float_as_uint(b)));
    return r;
}
__device__ __forceinline__ void ffma2(unsigned long long &d, unsigned long long a, unsigned long long b) {
    asm("fma.rn.f32x2 %0, %1, %2, %0;" : "+l"(d) : "l"(a), "l"(b));
}
__device__ __forceinline__ unsigned long long fadd2(unsigned long long a, unsigned long long b) {
    unsigned long long r;
    asm("add.rn.f32x2 %0, %1, %2;" : "=l"(r) : "l"(a), "l"(b));
    return r;
}
__device__ __forceinline__ float2 unpack2(unsigned long long v) {
    unsigned int lo, hi;
    asm("mov.b64 {%0, %1}, %2;" : "=r"(lo), "=r"(hi) : "l"(v));
    return make_float2(__uint_as_float(lo), __uint_as_float(hi));
}

// ---------- cp.async helpers ----------
__device__ __forceinline__ unsigned int smem_u32(const void* p) {
    unsigned int a;
    asm("{ .reg .u64 t; cvta.to.shared.u64 t, %1; cvt.u32.u64 %0, t; }" : "=r"(a) : "l"(p));
    return a;
}
__device__ __forceinline__ void cp16(unsigned int dst, const void* src) {
    asm volatile("cp.async.cg.shared.global [%0], [%1], 16;" :: "r"(dst), "l"(src));
}
#define CP_COMMIT() asm volatile("cp.async.commit_group;" ::: "memory")
#define CP_WAIT0()  asm volatile("cp.async.wait_group 0;" ::: "memory")

// ---------- K0a/K0b/K0c: init (split so k_fused is the 4th launch -> profiled) ----------
__global__ void __launch_bounds__(256) k_init_z() {
    g_z[threadIdx.x] = 0.f;
}
__global__ void __launch_bounds__(256) k_init_oa(const float* __restrict__ bout,
                                                 float* __restrict__ out) {
    int b = blockIdx.x;
    for (int i = threadIdx.x; i < F_; i += 256) out[b*F_ + i] = bout[i];
}
__global__ void __launch_bounds__(256) k_init_ob(const float* __restrict__ bout,
                                                 float* __restrict__ out) {
    int b = blockIdx.x + 16;
    for (int i = threadIdx.x; i < F_; i += 256) out[b*F_ + i] = bout[i];
}

// ---------- K_FUSED v6: fat warps (8 rows x 4 heads, v[32]), 1 block/SM, 255-reg cap ----
// grid (16, 32). Block: 128 rows = 4 super-iters of 32 rows = tiles A (warps 0-3,
// staged by threads 0-127) + B (warps 4-7 / threads 128-255), each 16 rows.
// Warp w: tile=w>>2, rowhalf=(w>>1)&1, hh=(w&1)*4. Phase 1: warp covers its 8 rows x
// 4 heads over ALL 768 f (x from its tile buffer, W from smem); single log-halving
// reduction per 32 outputs. Phase 2: all 256 threads, f-slice {tid,+256,+512}, both
// tiles. Restage A after phase2-A (hidden under phase2-B), B after phase2-B.
#define XBUF_ (16*F_*4)        // 48KB per tile buffer
#define SMEM_FUSED_ (H_*F_*8 + 2*XBUF_ + 2*16*8*4 + 64)

__global__ void __launch_bounds__(256, 1) k_fused(const float* __restrict__ x,
                                                  const float* __restrict__ Wa,
                                                  const float* __restrict__ Wg,
                                                  const float* __restrict__ bg) {
    extern __shared__ __align__(16) unsigned char dyn[];
    unsigned long long* Wp = reinterpret_cast<unsigned long long*>(dyn);     // 48KB
    float* xsA = reinterpret_cast<float*>(dyn + H_*F_*8);                    // 48KB
    float* xsB = reinterpret_cast<float*>(dyn + H_*F_*8 + XBUF_);            // 48KB
    float* wshA = reinterpret_cast<float*>(dyn + H_*F_*8 + 2*XBUF_);         // [16][8]
    float* wshB = wshA + 16*8;

    int tid = threadIdx.x, warp = tid >> 5, lane = tid & 31;
    int tile = warp >> 2, rowhalf = (warp >> 1) & 1, hh = (warp & 1) * 4;
    int half = tid >> 7;                       // staging half (== tile for this thread)
    int b = blockIdx.y, chunk = blockIdx.x;
    int row00 = b*S_ + chunk*128;

    // stage a 16-row tile buffer: 128 threads, 8 per row, 24 cp16 each, one group
    auto stagebuf = [&](float* dst, int grow0) {
        int t7 = tid & 127, r = t7 >> 3, p = t7 & 7;
        const float4* src = reinterpret_cast<const float4*>(
            x + (size_t)(grow0 + r)*F_) + p*24;
        unsigned int d = smem_u32(dst + r*F_) + (unsigned)p*24u*16u;
        #pragma unroll
        for (int j = 0; j < 24; j++) cp16(d + (unsigned)j*16u, src + j);
        CP_COMMIT();
    };

    stagebuf(half ? xsB : xsA, row00 + half*16);
    for (int i = tid; i < H_*F_; i += 256)     // W pack (L2-resident source)
        Wp[i] = pack2(Wa[i], Wg[i]);
    float bgv = bg[hh + (lane & 3)];
    __syncthreads();                           // Wp visible to all

    const float* xt = tile ? xsB : xsA;        // phase-1 source buffer
    float* wshT = tile ? wshB : wshA;

    unsigned long long acc[3][4];              // pooled accum: 3 f x 4 h-pairs
    #pragma unroll
    for (int i = 0; i < 3; i++)
        #pragma unroll
        for (int j = 0; j < 4; j++) acc[i][j] = 0ull;
    float zacc = 0.f;                          // lanes 0..3: head hh+lane

    #pragma unroll 1
    for (int t = 0; t < 4; t++) {
        // ---- phase 1: 8 rows x 4 heads over full f ----
        CP_WAIT0();                            // own half's staging complete
        asm volatile("bar.sync %0, 128;" :: "r"(half + 1) : "memory");
        {
            unsigned long long v[32];          // v[r*4 + h']
            #pragma unroll
            for (int i = 0; i < 32; i++) v[i] = 0ull;

            const float* xr = xt + (rowhalf*8)*F_ + 2*lane;
            #pragma unroll 2
            for (int c = 0; c < 12; c++) {
                float2 xv[8];
                #pragma unroll
                for (int r = 0; r < 8; r++)
                    xv[r] = *reinterpret_cast<const float2*>(xr + r*F_ + c*64);
                unsigned long long xb[16];
                #pragma unroll
                for (int r = 0; r < 8; r++) {
                    xb[2*r]   = bcast2(xv[r].x);
                    xb[2*r+1] = bcast2(xv[r].y);
                }
                int u = c*32 + lane;
                #pragma unroll
                for (int h = 0; h < 4; h++) {
                    ulonglong2 w2 = reinterpret_cast<const ulonglong2*>(Wp + (hh + h)*F_)[u];
                    #pragma unroll
                    for (int r = 0; r < 8; r++) {
                        ffma2(v[r*4 + h], xb[2*r],   w2.x);
                        ffma2(v[r*4 + h], xb[2*r+1], w2.y);
                    }
                }
            }

            // log-halving reduction: value i lands on lane i (32 values)
            #pragma unroll
            for (int s = 16; s >= 1; s >>= 1) {
                bool up = (lane & s) != 0;
                #pragma unroll
                for (int i = 0; i < s; i++) {
                    unsigned long long send = up ? v[i] : v[i+s];
                    unsigned long long recv = __shfl_xor_sync(0xffffffffu, send, s);
                    unsigned long long keep = up ? v[i+s] : v[i];
                    v[i] = fadd2(keep, recv);
                }
            }

            float2 res = unpack2(v[0]);        // lane l: r=l>>2, h'=l&3
            // no max-subtraction: logits ~ N(0,1); softmax shift-invariance (b_att cancels)
            float e = __expf(res.x);
            float wgt = e / (1.f + __expf(-(res.y + bgv)));
            wshT[(rowhalf*8 + (lane >> 2))*8 + hh + (lane & 3)] = wgt;
            e += __shfl_xor_sync(0xffffffffu, e, 4);     // sum over rows
            e += __shfl_xor_sync(0xffffffffu, e, 8);
            e += __shfl_xor_sync(0xffffffffu, e, 16);
            if (lane < 4) zacc += e;
        }
        __syncthreads();                       // wshA/wshB ready; phase1 done on both

        // ---- phase 2A: tile A rows ----
        #pragma unroll 2
        for (int sl = 0; sl < 16; sl++) {
            float x0 = xsA[sl*F_ + tid];
            float x1 = xsA[sl*F_ + tid + 256];
            float x2 = xsA[sl*F_ + tid + 512];
            unsigned long long b0 = bcast2(x0), b1 = bcast2(x1), b2 = bcast2(x2);
            ulonglong2 w01 = *reinterpret_cast<const ulonglong2*>(&wshA[sl*8]);
            ulonglong2 w23 = *reinterpret_cast<const ulonglong2*>(&wshA[sl*8 + 4]);
            unsigned long long wp[4] = {w01.x, w01.y, w23.x, w23.y};
            #pragma unroll
            for (int hp = 0; hp < 4; hp++) {
                ffma2(acc[0][hp], b0, wp[hp]);
                ffma2(acc[1][hp], b1, wp[hp]);
                ffma2(acc[2][hp], b2, wp[hp]);
            }
        }
        __syncthreads();                       // all done reading xsA
        if (t < 3 && half == 0)
            stagebuf(xsA, row00 + (t+1)*32);   // restage A (hides under phase2-B)

        // ---- phase 2B: tile B rows ----
        #pragma unroll 2
        for (int sl = 0; sl < 16; sl++) {
            float x0 = xsB[sl*F_ + tid];
            float x1 = xsB[sl*F_ + tid + 256];
            float x2 = xsB[sl*F_ + tid + 512];
            unsigned long long b0 = bcast2(x0), b1 = bcast2(x1), b2 = bcast2(x2);
            ulonglong2 w01 = *reinterpret_cast<const ulonglong2*>(&wshB[sl*8]);
            ulonglong2 w23 = *reinterpret_cast<const ulonglong2*>(&wshB[sl*8 + 4]);
            unsigned long long wp[4] = {w01.x, w01.y, w23.x, w23.y};
            #pragma unroll
            for (int hp = 0; hp < 4; hp++) {
                ffma2(acc[0][hp], b0, wp[hp]);
                ffma2(acc[1][hp], b1, wp[hp]);
                ffma2(acc[2][hp], b2, wp[hp]);
            }
        }
        __syncthreads();                       // all done reading xsB
        if (t < 3 && half == 1)
            stagebuf(xsB, row00 + (t+1)*32 + 16);   // restage B
    }

    if (lane < 4) atomicAdd(&g_z[b*8 + hh + lane], zacc);
    // write private partial slab (no atomics)
    unsigned long long* gp = reinterpret_cast<unsigned long long*>(
        g_part + (size_t)(b*CH_B_ + chunk)*KDIM_);
    #pragma unroll
    for (int fi = 0; fi < 3; fi++) {
        int f = tid + fi*256;
        #pragma unroll
        for (int hp = 0; hp < 4; hp++)
            gp[f*4 + hp] = acc[fi][hp];
    }
}

// ---------- K_NORM: g_pooled = (sum of 16 partial slabs) / Z ----------
__global__ void __launch_bounds__(256) k_norm() {
    __shared__ float iz[8];
    int b = blockIdx.x >> 1, half = blockIdx.x & 1;      // 64 blocks
    if (threadIdx.x < 8) iz[threadIdx.x] = 1.f / g_z[b*8 + threadIdx.x];
    __syncthreads();
    #pragma unroll
    for (int j = 0; j < 3; j++) {
        int idx4 = half*768 + j*256 + threadIdx.x;       // float4 index in batch slab
        float4 s = make_float4(0.f, 0.f, 0.f, 0.f);
        #pragma unroll
        for (int p = 0; p < CH_B_; p++) {
            float4 v = reinterpret_cast<const float4*>(
                g_part + (size_t)(b*CH_B_ + p)*KDIM_)[idx4];
            s.x += v.x; s.y += v.y; s.z += v.z; s.w += v.w;
        }
        int hb = (idx4 & 1) * 4;
        s.x *= iz[hb]; s.y *= iz[hb+1]; s.z *= iz[hb+2]; s.w *= iz[hb+3];
        reinterpret_cast<float4*>(g_pooled + (size_t)b*KDIM_)[idx4] = s;
    }
}

// ---------- K4: out += pooled @ Wout^T  (576 blocks, double-buffered, swizzled) ----------
#define NT_ 64       // output-column tile per block (grid.x = 12)
#define KT_ 128      // K range per block (grid.y = 48)
#define KSUB_ 64     // K staged per buffer (32 ull units)

__global__ void __launch_bounds__(256) k_out4(const float* __restrict__ Wout,
                                              float* __restrict__ out) {
    __shared__ unsigned long long ws[2][NT_][32];        // rotation-swizzled: phys=(k+col)&31
    __shared__ unsigned long long ps[2][32][32];
    int n0 = blockIdx.x * NT_;
    int k0h = blockIdx.y * (KT_/2);                      // in float2 units
    int cidx = threadIdx.x & 31;
    int bq   = threadIdx.x >> 5;
    const float2* W2 = reinterpret_cast<const float2*>(Wout);
    const float2* P2 = reinterpret_cast<const float2*>(g_pooled);

    int wc = threadIdx.x >> 5;
    int kq = threadIdx.x & 31;

    float2 rw[8], rp[4];
    #pragma unroll
    for (int s = 0; s < 8; s++)
        rw[s] = W2[(size_t)(n0 + wc + s*8)*(KDIM_/2) + k0h + kq];
    #pragma unroll
    for (int s = 0; s < 4; s++)
        rp[s] = P2[(size_t)(wc + s*8)*(KDIM_/2) + k0h + kq];
    #pragma unroll
    for (int s = 0; s < 8; s++)
        ws[0][wc + s*8][(kq + wc + s*8) & 31] = pack2(rw[s].x, rw[s].y);
    #pragma unroll
    for (int s = 0; s < 4; s++)
        ps[0][wc + s*8][kq] = pack2(rp[s].x, rp[s].y);
    __syncthreads();

    unsigned long long acc[4][2];
    #pragma unroll
    for (int r = 0; r < 4; r++) { acc[r][0] = 0ull; acc[r][1] = 0ull; }

    #pragma unroll
    for (int sub = 0; sub < KT_/KSUB_; sub++) {
        if (sub < KT_/KSUB_ - 1) {
            int kh = k0h + (sub+1)*32;
            #pragma unroll
            for (int s = 0; s < 8; s++)
                rw[s] = W2[(size_t)(n0 + wc + s*8)*(KDIM_/2) + kh + kq];
            #pragma unroll
            for (int s = 0; s < 4; s++)
                rp[s] = P2[(size_t)(wc + s*8)*(KDIM_/2) + kh + kq];
        }
        int buf = sub & 1;
        #pragma unroll 8
        for (int kk = 0; kk < 32; kk++) {
            int ph = (kk + cidx) & 31;
            unsigned long long wv0 = ws[buf][cidx][ph];
            unsigned long long wv1 = ws[buf][cidx + 32][ph];
            #pragma unroll
            for (int r = 0; r < 4; r++) {
                unsigned long long pv = ps[buf][bq*4 + r][kk];
                ffma2(acc[r][0], pv, wv0);
                ffma2(acc[r][1], pv, wv1);
            }
        }
        if (sub < KT_/KSUB_ - 1) {
            int nb = (sub + 1) & 1;
            #pragma unroll
            for (int s = 0; s < 8; s++)
                ws[nb][wc + s*8][(kq + wc + s*8) & 31] = pack2(rw[s].x, rw[s].y);
            #pragma unroll
            for (int s = 0; s < 4; s++)
                ps[nb][wc + s*8][kq] = pack2(rp[s].x, rp[s].y);
            __syncthreads();
        }
    }

    #pragma unroll
    for (int r = 0; r < 4; r++)
        #pragma unroll
        for (int c = 0; c < 2; c++) {
            float2 v = unpack2(acc[r][c]);
            atomicAdd(&out[(size_t)(bq*4 + r)*F_ + n0 + cidx + c*32], v.x + v.y);
        }
}

extern "C" void kernel_launch(void* const* d_in, const int* in_sizes, int n_in,
                              void* d_out, int out_size) {
    const float* x    = (const float*)d_in[0];   // [B,S,F]
    const float* Wa   = (const float*)d_in[1];   // [H,F]
    // d_in[2] = b_att: unused (softmax over s is shift-invariant per (b,h))
    const float* Wg   = (const float*)d_in[3];   // [H,F]
    const float* bg   = (const float*)d_in[4];   // [H]
    const float* Wout = (const float*)d_in[5];   // [F, H*F]
    const float* bout = (const float*)d_in[6];   // [F]
    float* out = (float*)d_out;                  // [B,F]

    static int smem_set = 0;
    if (!smem_set) {
        cudaFuncSetAttribute(k_fused, cudaFuncAttributeMaxDynamicSharedMemorySize,
                             SMEM_FUSED_);
        smem_set = 1;
    }

    k_init_z<<<1, 256>>>();
    k_init_oa<<<16, 256>>>(bout, out);
    k_init_ob<<<16, 256>>>(bout, out);
    k_fused<<<dim3(CH_B_, B_), 256, SMEM_FUSED_>>>(x, Wa, Wg, bg);   // 4th launch -> profiled
    k_norm<<<2*B_, 256>>>();
    k_out4<<<dim3(F_/NT_, KDIM_/KT_), 256>>>(Wout, out);
}

// round 12
// speedup vs baseline: 1.3663x; 1.3453x over previous
#include <cuda_runtime.h>

#define B_ 32
#define S_ 2048
#define F_ 768
#define H_ 8
#define KDIM_ (F_*H_)          // 6144
#define T_TILES_ 8             // 16-row tiles per block
#define CH_B_ 16               // chunks per batch (2048 / 128)
#define NPART_ (B_*CH_B_)      // 512 partial slabs

// Scratch (device globals; no runtime allocation)
__device__ float g_z[B_*H_];               // softmax denominators (atomic-accumulated)
__device__ float g_part[NPART_*KDIM_];     // per-block partial pooled slabs
__device__ float g_pooled[B_*KDIM_];       // normalized pooled [b][f][h]

// ---------- packed f32x2 helpers ----------
__device__ __forceinline__ unsigned long long bcast2(float v) {
    unsigned int u = __float_as_uint(v);
    unsigned long long r;
    asm("mov.b64 %0, {%1, %1};" : "=l"(r) : "r"(u));
    return r;
}
__device__ __forceinline__ unsigned long long pack2(float a, float b) {
    unsigned long long r;
    asm("mov.b64 %0, {%1, %2};" : "=l"(r)
        : "r"(__float_as_uint(a)), "r"(__float_as_uint(b)));
    return r;
}
__device__ __forceinline__ void ffma2(unsigned long long &d, unsigned long long a, unsigned long long b) {
    asm("fma.rn.f32x2 %0, %1, %2, %0;" : "+l"(d) : "l"(a), "l"(b));
}
__device__ __forceinline__ unsigned long long fadd2(unsigned long long a, unsigned long long b) {
    unsigned long long r;
    asm("add.rn.f32x2 %0, %1, %2;" : "=l"(r) : "l"(a), "l"(b));
    return r;
}
__device__ __forceinline__ float2 unpack2(unsigned long long v) {
    unsigned int lo, hi;
    asm("mov.b64 {%0, %1}, %2;" : "=r"(lo), "=r"(hi) : "l"(v));
    return make_float2(__uint_as_float(lo), __uint_as_float(hi));
}

// ---------- cp.async helpers ----------
__device__ __forceinline__ unsigned int smem_u32(const void* p) {
    unsigned int a;
    asm("{ .reg .u64 t; cvta.to.shared.u64 t, %1; cvt.u32.u64 %0, t; }" : "=r"(a) : "l"(p));
    return a;
}
__device__ __forceinline__ void cp16(unsigned int dst, const void* src) {
    asm volatile("cp.async.cg.shared.global [%0], [%1], 16;" :: "r"(dst), "l"(src));
}
#define CP_COMMIT() asm volatile("cp.async.commit_group;" ::: "memory")
#define CP_WAIT0()  asm volatile("cp.async.wait_group 0;" ::: "memory")

// ---------- K0a/K0b/K0c: init (split so k_fused is the 4th launch -> profiled) ----------
__global__ void __launch_bounds__(256) k_init_z() {
    g_z[threadIdx.x] = 0.f;
}
__global__ void __launch_bounds__(256) k_init_oa(const float* __restrict__ bout,
                                                 float* __restrict__ out) {
    int b = blockIdx.x;
    for (int i = threadIdx.x; i < F_; i += 256) out[b*F_ + i] = bout[i];
}
__global__ void __launch_bounds__(256) k_init_ob(const float* __restrict__ bout,
                                                 float* __restrict__ out) {
    int b = blockIdx.x + 16;
    for (int i = threadIdx.x; i < F_; i += 256) out[b*F_ + i] = bout[i];
}

// ---------- K_FUSED v7: R8 structure, single-group half staging, minimal barriers ----
// grid (CH_B_, B_). Block: 128 rows = 8 tiles of 16 rows, as 8-row halves A/B.
// Staging: half A owned by tids 0-127, half B by tids 128-255; ONE cp group per half.
// Phase 1: warp w: pid=w>>1 (rows pid*4..+3), hh=(w&1)*4 (4 heads). Warps 0-3 read
//   half A (their stager threads), warps 4-7 half B -> wait_group 0 + named bar(128).
// Phase 2: all threads, f-slice {tid,+256,+512}; 2A then restage A, 2B then restage B.
#define XHALF_ (8*F_*4)        // 24KB per half
#define SMEM_FUSED_ (H_*F_*8 + 2*XHALF_ + 16*8*4 + 64)

__global__ void __launch_bounds__(256, 2) k_fused(const float* __restrict__ x,
                                                  const float* __restrict__ Wa,
                                                  const float* __restrict__ Wg,
                                                  const float* __restrict__ bg) {
    extern __shared__ __align__(16) unsigned char dyn[];
    unsigned long long* Wp = reinterpret_cast<unsigned long long*>(dyn);     // 48KB
    float* xa  = reinterpret_cast<float*>(dyn + H_*F_*8);                    // [8][768]
    float* xb  = reinterpret_cast<float*>(dyn + H_*F_*8 + XHALF_);           // [8][768]
    float* wsh = reinterpret_cast<float*>(dyn + H_*F_*8 + 2*XHALF_);         // [16][8]

    int tid = threadIdx.x, warp = tid >> 5, lane = tid & 31;
    int pid = warp >> 1, hh = (warp & 1) * 4;
    int half = tid >> 7;                       // 0: owns A, 1: owns B (== pid>=2 side)
    int b = blockIdx.y, chunk = blockIdx.x;
    int row00 = b*S_ + chunk*(16*T_TILES_);
    unsigned int xab = smem_u32(xa), xbb = smem_u32(xb);

    // stage own 8-row half: 128 threads, 16 per row, 12 float4 each, ONE group
    auto stage_half = [&](unsigned int dstb, int grow0) {
        int t7 = tid & 127, r = t7 >> 4, p = t7 & 15;
        const float4* src = reinterpret_cast<const float4*>(x + (size_t)(grow0 + r)*F_);
        unsigned int d = dstb + (unsigned)(r*768)*4u;
        #pragma unroll
        for (int j = 0; j < 12; j++)
            cp16(d + (unsigned)((p + j*16)*4)*4u, src + p + j*16);
        CP_COMMIT();
    };

    stage_half(half ? xbb : xab, row00 + half*8);   // own half of tile 0
    for (int i = tid; i < H_*F_; i += 256)          // W pack (L2-resident source)
        Wp[i] = pack2(Wa[i], Wg[i]);
    float bgv = bg[hh + (lane & 3)];
    __syncthreads();                                // Wp visible

    const float* xsrc = (pid < 2) ? xa : xb;        // phase-1 source half
    int rbase = (pid & 1) * 4;                      // rows rbase..rbase+3 within half

    unsigned long long acc[3][4];                   // pooled accum: 3 f x 4 h-pairs
    #pragma unroll
    for (int i = 0; i < 3; i++)
        #pragma unroll
        for (int j = 0; j < 4; j++) acc[i][j] = 0ull;
    float zacc = 0.f;                               // lanes 0..3: head hh+lane

    #pragma unroll 1
    for (int t = 0; t < T_TILES_; t++) {
        // ---- phase 1: rows pid*4..+3, heads hh..hh+3 ----
        CP_WAIT0();                                 // own half staged
        asm volatile("bar.sync %0, 128;" :: "r"(half + 1) : "memory");
        {
            unsigned long long v[16];               // v[r*4 + h'] = (att, gate)
            #pragma unroll
            for (int i = 0; i < 16; i++) v[i] = 0ull;

            #pragma unroll 4
            for (int c = 0; c < 12; c++) {
                float2 xv[4];
                #pragma unroll
                for (int r = 0; r < 4; r++)
                    xv[r] = *reinterpret_cast<const float2*>(
                        &xsrc[(rbase + r)*F_ + c*64 + lane*2]);
                unsigned long long xb2[8];
                #pragma unroll
                for (int r = 0; r < 4; r++) {
                    xb2[2*r]   = bcast2(xv[r].x);
                    xb2[2*r+1] = bcast2(xv[r].y);
                }
                int u = c*32 + lane;
                #pragma unroll
                for (int h = 0; h < 4; h++) {
                    ulonglong2 w = reinterpret_cast<const ulonglong2*>(Wp + (hh + h)*F_)[u];
                    #pragma unroll
                    for (int r = 0; r < 4; r++) {
                        ffma2(v[r*4 + h], xb2[2*r],   w.x);
                        ffma2(v[r*4 + h], xb2[2*r+1], w.y);
                    }
                }
            }

            // reduce 16 packed values across 32 lanes: value i -> lane i (0..15)
            #pragma unroll
            for (int i = 0; i < 16; i++)
                v[i] = fadd2(v[i], __shfl_xor_sync(0xffffffffu, v[i], 16));
            #pragma unroll
            for (int s = 8; s >= 1; s >>= 1) {
                bool up = (lane & s) != 0;
                #pragma unroll
                for (int i = 0; i < s; i++) {
                    unsigned long long send = up ? v[i] : v[i+s];
                    unsigned long long recv = __shfl_xor_sync(0xffffffffu, send, s);
                    unsigned long long keep = up ? v[i+s] : v[i];
                    v[i] = fadd2(keep, recv);
                }
            }

            float2 res = unpack2(v[0]);             // lane<16: r=lane>>2, h'=lane&3
            // no max-subtraction: logits ~ N(0,1); softmax shift-invariance (b_att cancels)
            float e = __expf(res.x);
            float wgt = e / (1.f + __expf(-(res.y + bgv)));
            if (lane < 16)
                wsh[(pid*4 + (lane >> 2))*8 + hh + (lane & 3)] = wgt;
            float ez = e;
            ez += __shfl_xor_sync(0xffffffffu, ez, 4);
            ez += __shfl_xor_sync(0xffffffffu, ez, 8);
            if (lane < 4) zacc += ez;
        }
        __syncthreads();                            // wsh ready; phase1 done on both halves

        int c0 = tid >> 6, q = tid & 63;            // f = c0*64+q (+256,+512 variants)
        // ---- phase 2A: rows 0..7 from xa ----
        #pragma unroll 4
        for (int sl = 0; sl < 8; sl++) {
            float x0 = xa[sl*F_ + c0*64 + q];
            float x1 = xa[sl*F_ + c0*64 + q + 256];
            float x2 = xa[sl*F_ + c0*64 + q + 512];
            unsigned long long b0 = bcast2(x0), b1 = bcast2(x1), b2 = bcast2(x2);
            ulonglong2 w01 = *reinterpret_cast<const ulonglong2*>(&wsh[sl*8]);
            ulonglong2 w23 = *reinterpret_cast<const ulonglong2*>(&wsh[sl*8 + 4]);
            unsigned long long wp[4] = {w01.x, w01.y, w23.x, w23.y};
            #pragma unroll
            for (int hp = 0; hp < 4; hp++) {
                ffma2(acc[0][hp], b0, wp[hp]);
                ffma2(acc[1][hp], b1, wp[hp]);
                ffma2(acc[2][hp], b2, wp[hp]);
            }
        }
        __syncthreads();                            // all done reading xa
        if (t + 1 < T_TILES_ && half == 0)
            stage_half(xab, row00 + (t+1)*16);      // restage A (hides under phase2-B)

        // ---- phase 2B: rows 8..15 from xb ----
        #pragma unroll 4
        for (int sl = 0; sl < 8; sl++) {
            float x0 = xb[sl*F_ + c0*64 + q];
            float x1 = xb[sl*F_ + c0*64 + q + 256];
            float x2 = xb[sl*F_ + c0*64 + q + 512];
            unsigned long long b0 = bcast2(x0), b1 = bcast2(x1), b2 = bcast2(x2);
            ulonglong2 w01 = *reinterpret_cast<const ulonglong2*>(&wsh[(8+sl)*8]);
            ulonglong2 w23 = *reinterpret_cast<const ulonglong2*>(&wsh[(8+sl)*8 + 4]);
            unsigned long long wp[4] = {w01.x, w01.y, w23.x, w23.y};
            #pragma unroll
            for (int hp = 0; hp < 4; hp++) {
                ffma2(acc[0][hp], b0, wp[hp]);
                ffma2(acc[1][hp], b1, wp[hp]);
                ffma2(acc[2][hp], b2, wp[hp]);
            }
        }
        __syncthreads();                            // all done reading xb
        if (t + 1 < T_TILES_ && half == 1)
            stage_half(xbb, row00 + (t+1)*16 + 8);  // restage B
    }

    if (lane < 4) atomicAdd(&g_z[b*8 + hh + lane], zacc);
    // write private partial slab (no atomics); note phase2 f-slice is {c0*64+q + fi*256}
    {
        int f0 = (tid >> 6)*64 + (tid & 63);
        unsigned long long* gp = reinterpret_cast<unsigned long long*>(
            g_part + (size_t)(b*CH_B_ + chunk)*KDIM_);
        #pragma unroll
        for (int fi = 0; fi < 3; fi++) {
            int f = f0 + fi*256;
            #pragma unroll
            for (int hp = 0; hp < 4; hp++)
                gp[f*4 + hp] = acc[fi][hp];
        }
    }
}

// ---------- K_NORM: g_pooled = (sum of 16 partial slabs) / Z  (128 blocks) ----------
__global__ void __launch_bounds__(256) k_norm() {
    __shared__ float iz[8];
    int b = blockIdx.x >> 2, quarter = blockIdx.x & 3;   // 128 blocks
    if (threadIdx.x < 8) iz[threadIdx.x] = 1.f / g_z[b*8 + threadIdx.x];
    __syncthreads();
    #pragma unroll
    for (int j = 0; j < 2; j++) {
        int loc = j*256 + threadIdx.x;
        if (loc >= 384) break;
        int idx4 = quarter*384 + loc;                    // float4 index in batch slab
        float4 s = make_float4(0.f, 0.f, 0.f, 0.f);
        #pragma unroll
        for (int p = 0; p < CH_B_; p++) {
            float4 v = reinterpret_cast<const float4*>(
                g_part + (size_t)(b*CH_B_ + p)*KDIM_)[idx4];
            s.x += v.x; s.y += v.y; s.z += v.z; s.w += v.w;
        }
        int hb = (idx4 & 1) * 4;
        s.x *= iz[hb]; s.y *= iz[hb+1]; s.z *= iz[hb+2]; s.w *= iz[hb+3];
        reinterpret_cast<float4*>(g_pooled + (size_t)b*KDIM_)[idx4] = s;
    }
}

// ---------- K4: out += pooled @ Wout^T  (1152 blocks, swizzled) ----------
#define NT_ 64       // output-column tile per block (grid.x = 12)
#define KT_ 64       // K range per block (grid.y = 96)
#define KSUB_ 64     // K staged per buffer (32 ull units)

__global__ void __launch_bounds__(256) k_out4(const float* __restrict__ Wout,
                                              float* __restrict__ out) {
    __shared__ unsigned long long ws[2][NT_][32];        // rotation-swizzled: phys=(k+col)&31
    __shared__ unsigned long long ps[2][32][32];
    int n0 = blockIdx.x * NT_;
    int k0h = blockIdx.y * (KT_/2);                      // in float2 units
    int cidx = threadIdx.x & 31;
    int bq   = threadIdx.x >> 5;
    const float2* W2 = reinterpret_cast<const float2*>(Wout);
    const float2* P2 = reinterpret_cast<const float2*>(g_pooled);

    int wc = threadIdx.x >> 5;
    int kq = threadIdx.x & 31;

    float2 rw[8], rp[4];
    #pragma unroll
    for (int s = 0; s < 8; s++)
        rw[s] = W2[(size_t)(n0 + wc + s*8)*(KDIM_/2) + k0h + kq];
    #pragma unroll
    for (int s = 0; s < 4; s++)
        rp[s] = P2[(size_t)(wc + s*8)*(KDIM_/2) + k0h + kq];
    #pragma unroll
    for (int s = 0; s < 8; s++)
        ws[0][wc + s*8][(kq + wc + s*8) & 31] = pack2(rw[s].x, rw[s].y);
    #pragma unroll
    for (int s = 0; s < 4; s++)
        ps[0][wc + s*8][kq] = pack2(rp[s].x, rp[s].y);
    __syncthreads();

    unsigned long long acc[4][2];
    #pragma unroll
    for (int r = 0; r < 4; r++) { acc[r][0] = 0ull; acc[r][1] = 0ull; }

    #pragma unroll
    for (int sub = 0; sub < KT_/KSUB_; sub++) {
        int buf = sub & 1;
        #pragma unroll 8
        for (int kk = 0; kk < 32; kk++) {
            int ph = (kk + cidx) & 31;
            unsigned long long wv0 = ws[buf][cidx][ph];
            unsigned long long wv1 = ws[buf][cidx + 32][ph];
            #pragma unroll
            for (int r = 0; r < 4; r++) {
                unsigned long long pv = ps[buf][bq*4 + r][kk];
                ffma2(acc[r][0], pv, wv0);
                ffma2(acc[r][1], pv, wv1);
            }
        }
    }

    #pragma unroll
    for (int r = 0; r < 4; r++)
        #pragma unroll
        for (int c = 0; c < 2; c++) {
            float2 v = unpack2(acc[r][c]);
            atomicAdd(&out[(size_t)(bq*4 + r)*F_ + n0 + cidx + c*32], v.x + v.y);
        }
}

extern "C" void kernel_launch(void* const* d_in, const int* in_sizes, int n_in,
                              void* d_out, int out_size) {
    const float* x    = (const float*)d_in[0];   // [B,S,F]
    const float* Wa   = (const float*)d_in[1];   // [H,F]
    // d_in[2] = b_att: unused (softmax over s is shift-invariant per (b,h))
    const float* Wg   = (const float*)d_in[3];   // [H,F]
    const float* bg   = (const float*)d_in[4];   // [H]
    const float* Wout = (const float*)d_in[5];   // [F, H*F]
    const float* bout = (const float*)d_in[6];   // [F]
    float* out = (float*)d_out;                  // [B,F]

    static int smem_set = 0;
    if (!smem_set) {
        cudaFuncSetAttribute(k_fused, cudaFuncAttributeMaxDynamicSharedMemorySize,
                             SMEM_FUSED_);
        smem_set = 1;
    }

    k_init_z<<<1, 256>>>();
    k_init_oa<<<16, 256>>>(bout, out);
    k_init_ob<<<16, 256>>>(bout, out);
    k_fused<<<dim3(CH_B_, B_), 256, SMEM_FUSED_>>>(x, Wa, Wg, bg);   // 4th launch -> profiled
    k_norm<<<4*B_, 256>>>();
    k_out4<<<dim3(F_/NT_, KDIM_/KT_), 256>>>(Wout, out);
}